// round 9
// baseline (speedup 1.0000x reference)
#include <cuda_runtime.h>

// EMA over x[32, 4096, 256] fp32, adjust=True, period=25.
// Round-9: raise memory-controller stream parallelism via warp count.
// 16 chunks of 256 with warmup 128 (oma^128 ~ 3.5e-5 << 1e-3) -> 4096 warps
// (27.7/SM, ~40% occ) vs R6's 2048. Pipeline depth back to 2 (UB=16,
// 32 LDGs in flight/warp): per-warp MLP was saturated; total in-flight
// bytes/SM still rises (113KB vs 84KB). Normal STG stores (proven best).

#define B_DIM   32
#define T_DIM   4096
#define F_DIM   256
#define CHUNK   256
#define NCHUNK  16
#define WARMUP  128
#define UB      16
#define NB_MAIN ((WARMUP + CHUNK) / UB)   // 24
#define NB_ZERO (CHUNK / UB)              // 16
#define WARM_B  (WARMUP / UB)             // 8

#define ALPHA_C (2.0f / 26.0f)
#define OMA_C   (1.0f - ALPHA_C)

__device__ __forceinline__ void load_batch(float (&d)[UB],
                                           const float* __restrict__ p) {
#pragma unroll
    for (int i = 0; i < UB; i++)
        d[i] = __ldg(p + (size_t)i * F_DIM);
}

// Constant-coefficient batch (w_t == 1.0f exactly in fp32 for t >= 207;
// all chunks >= 1 start reading at t >= 128 but only STORE at t >= 256).
__device__ __forceinline__ void proc_const(const float (&xv)[UB], float& e,
                                           float* __restrict__ po, bool st) {
#pragma unroll
    for (int i = 0; i < UB; i++) {
        e = fmaf(OMA_C, e, ALPHA_C * xv[i]);
        if (st) po[(size_t)i * F_DIM] = e;
    }
}

// Exact adjusted recurrence; p0 = oma^{t0} on entry. Reciprocals off-chain.
__device__ __forceinline__ void proc_adj(const float (&xv)[UB], float& e,
                                         float& p0, float* __restrict__ po) {
    float rw[UB];
    float q = 1.0f;
#pragma unroll
    for (int i = 0; i < UB; i++) {
        q *= OMA_C;                    // compile-time powers
        float wt = 1.0f - p0 * q;      // >= alpha, never degenerate
        rw[i] = __fdividef(1.0f, wt);
    }
    p0 *= q;
#pragma unroll
    for (int i = 0; i < UB; i++) {
        e = fmaf(OMA_C * rw[i], e, (ALPHA_C * rw[i]) * xv[i]);
        po[(size_t)i * F_DIM] = e;
    }
}

// NOTE on warmup validity: chunks >= 1 start 128 steps early from e=0 with
// constant coefficients. For chunk 1 the warmup covers t in [128, 256) where
// the true recurrence still divides by w_t for t < 207; however the warmup
// state enters the stored region attenuated by oma^128 ~ 3.5e-5, so both the
// truncation (dropping t < t_start-128) and the w_t!=1 coefficient error in
// the warmup are bounded by ~3.5e-5 relative -- 30x under the 1e-3 gate.

__global__ void __launch_bounds__(64)
ema_wide_kernel(const float* __restrict__ x, float* __restrict__ out) {
    int g     = blockIdx.x * 64 + threadIdx.x;
    int lane  = g & 31;
    int w     = g >> 5;                 // warp id 0..4095
    int f_hi  = w & 7;                  // 8 f-groups of 32 features
    int chunk = (w >> 3) & (NCHUNK - 1);
    int b     = w >> 7;                 // 0..31
    int f     = f_hi * 32 + lane;

    size_t seq_base = ((size_t)b * T_DIM) * F_DIM + f;
    const size_t STRIDE = (size_t)UB * F_DIM;
    float* __restrict__ po = out + seq_base + (size_t)chunk * CHUNK * F_DIM;

    float e = 0.0f;
    float buf0[UB], buf1[UB];

    if (chunk == 0) {
        // 256 exact-adjusted steps from t=0 (e_{-1}=0 gives e_0 = x_0).
        const float* __restrict__ px = x + seq_base;
        float p0 = 1.0f;
        load_batch(buf0, px); px += STRIDE;
#pragma unroll 1
        for (int bt = 0; bt < NB_ZERO; bt += 2) {
            load_batch(buf1, px); px += STRIDE;
            proc_adj(buf0, e, p0, po); po += STRIDE;
            if (bt + 2 < NB_ZERO) { load_batch(buf0, px); px += STRIDE; }
            proc_adj(buf1, e, p0, po); po += STRIDE;
        }
    } else {
        // 128 warmup steps (no store) + 256 constant-coefficient steps.
        const float* __restrict__ px =
            x + seq_base + ((size_t)chunk * CHUNK - WARMUP) * F_DIM;
        load_batch(buf0, px); px += STRIDE;
#pragma unroll 1
        for (int bt = 0; bt < NB_MAIN; bt += 2) {
            load_batch(buf1, px); px += STRIDE;
            bool s0 = (bt >= WARM_B);
            proc_const(buf0, e, po, s0);
            if (s0) po += STRIDE;
            if (bt + 2 < NB_MAIN) { load_batch(buf0, px); px += STRIDE; }
            bool s1 = (bt + 1 >= WARM_B);
            proc_const(buf1, e, po, s1);
            if (s1) po += STRIDE;
        }
    }
}

extern "C" void kernel_launch(void* const* d_in, const int* in_sizes, int n_in,
                              void* d_out, int out_size) {
    const float* x = (const float*)d_in[0];
    float* out = (float*)d_out;
    // 32 b * 16 chunks * 8 f-groups = 4096 warps, 2 per block -> 2048 blocks
    ema_wide_kernel<<<2048, 64>>>(x, out);
}

// round 10
// speedup vs baseline: 1.0197x; 1.0197x over previous
#include <cuda_runtime.h>

// EMA over x[32, 4096, 256] fp32, adjust=True, period=25.
// Round-10: R6 settings (proven at the ~5.8TB/s mixed-R/W ceiling: scalar
// lanes, 2048 warps in 64-thread blocks, UB=16 depth-3 pipeline = 48 LDGs in
// flight/warp, normal STG) with exact work balance:
//   chunk 0: steps [0, 736), all stored (adjusted recurrence for t<256,
//            constant coefficients after -- w_t == 1.0f in fp32 for t>=207)
//   chunks 1..7: 256 warmup steps (no store, oma^256 ~ 1.2e-9) + 480 stored
// Every warp processes exactly 46 batches of 16 steps -> no straggler tail.

#define B_DIM   32
#define T_DIM   4096
#define F_DIM   256
#define NCHUNK  8
#define L_MAIN  480
#define L_ZERO  736            // 736 + 7*480 = 4096
#define WARMUP  256
#define UB      16
#define NB      46             // batches per warp (identical for all warps)
#define PH      16             // first-phase batches (adj / warmup)

#define ALPHA_C (2.0f / 26.0f)
#define OMA_C   (1.0f - ALPHA_C)

__device__ __forceinline__ void load_batch(float (&d)[UB],
                                           const float* __restrict__ p) {
#pragma unroll
    for (int i = 0; i < UB; i++)
        d[i] = __ldg(p + (size_t)i * F_DIM);
}

// Constant-coefficient batch (w_t == 1.0f exactly in fp32 for t >= 207).
__device__ __forceinline__ void proc_const(const float (&xv)[UB], float& e,
                                           float* __restrict__ po, bool st) {
#pragma unroll
    for (int i = 0; i < UB; i++) {
        e = fmaf(OMA_C, e, ALPHA_C * xv[i]);
        if (st) po[(size_t)i * F_DIM] = e;
    }
}

// Exact adjusted recurrence; p0 = oma^{t0} on entry. Reciprocals off-chain.
__device__ __forceinline__ void proc_adj(const float (&xv)[UB], float& e,
                                         float& p0, float* __restrict__ po) {
    float rw[UB];
    float q = 1.0f;
#pragma unroll
    for (int i = 0; i < UB; i++) {
        q *= OMA_C;                    // compile-time powers
        float wt = 1.0f - p0 * q;      // >= alpha, never degenerate
        rw[i] = __fdividef(1.0f, wt);
    }
    p0 *= q;
#pragma unroll
    for (int i = 0; i < UB; i++) {
        e = fmaf(OMA_C * rw[i], e, (ALPHA_C * rw[i]) * xv[i]);
        po[(size_t)i * F_DIM] = e;
    }
}

__global__ void __launch_bounds__(64)
ema_bal3_kernel(const float* __restrict__ x, float* __restrict__ out) {
    int g     = blockIdx.x * 64 + threadIdx.x;
    int lane  = g & 31;
    int w     = g >> 5;                 // warp id 0..2047
    int f_hi  = w & 7;
    int chunk = (w >> 3) & (NCHUNK - 1);
    int b     = w >> 6;
    int f     = f_hi * 32 + lane;
    bool isZ  = (chunk == 0);

    int t_store = isZ ? 0 : L_ZERO + (chunk - 1) * L_MAIN;
    int t_read  = isZ ? 0 : t_store - WARMUP;

    size_t seq_base = ((size_t)b * T_DIM) * F_DIM + f;
    const size_t STRIDE = (size_t)UB * F_DIM;
    const float* __restrict__ px = x   + seq_base + (size_t)t_read  * F_DIM;
    float*       __restrict__ po = out + seq_base + (size_t)t_store * F_DIM;

    float e  = 0.0f;
    float p0 = 1.0f;
    float bA[UB], bB[UB], bC[UB], bD[UB];

    load_batch(bA, px); px += STRIDE;
    load_batch(bB, px); px += STRIDE;
    load_batch(bC, px); px += STRIDE;

    // proc(j) for batch index j:
    //  chunk0, j <  PH : proc_adj   (stores)
    //  chunk0, j >= PH : proc_const (stores)   [t >= 256 -> w_t == 1.0f]
    //  other,  j <  PH : proc_const no-store   (warmup)
    //  other,  j >= PH : proc_const store
#define PROC(j, buf)                                                      \
    do {                                                                  \
        if (isZ && (j) < PH) { proc_adj(buf, e, p0, po); po += STRIDE; }  \
        else {                                                            \
            bool _st = isZ || ((j) >= PH);                                \
            proc_const(buf, e, po, _st);                                  \
            if (_st) po += STRIDE;                                        \
        }                                                                 \
    } while (0)

#pragma unroll 1
    for (int bt = 0; bt < NB - 2; bt += 4) {     // 11 iterations (44 batches)
        load_batch(bD, px); px += STRIDE;                 // bt+3
        PROC(bt, bA);
        if (bt + 4 < NB) { load_batch(bA, px); px += STRIDE; }
        PROC(bt + 1, bB);
        if (bt + 5 < NB) { load_batch(bB, px); px += STRIDE; }
        PROC(bt + 2, bC);
        if (bt + 6 < NB) { load_batch(bC, px); px += STRIDE; }
        PROC(bt + 3, bD);
    }
    // Epilogue: batches 44, 45 (in bA, bB; all loads done)
    PROC(NB - 2, bA);
    PROC(NB - 1, bB);
#undef PROC
}

extern "C" void kernel_launch(void* const* d_in, const int* in_sizes, int n_in,
                              void* d_out, int out_size) {
    const float* x = (const float*)d_in[0];
    float* out = (float*)d_out;
    // 32 b * 8 chunks * 8 f-groups = 2048 warps, 2 per block -> 1024 blocks
    ema_bal3_kernel<<<1024, 64>>>(x, out);
}

// round 11
// speedup vs baseline: 1.1151x; 1.0936x over previous
#include <cuda_runtime.h>

// EMA over x[32, 4096, 256] fp32, adjust=True, period=25.
// Round-11: balanced + minimal-redundancy partition.
//   chunk 0: t in [0, 624), all stored; exact adjusted recurrence for the
//            first 13 batches (t < 208, where w_t != 1.0f in fp32), constant
//            coefficients after.
//   chunks 1..7: 128 warmup steps from e=0 (oma^128 ~ 3.5e-5; measured in
//            R9 to leave rel_err at 2.8e-6) + 496 stored steps.
// Every warp: exactly 39 batches of 16 steps (624). Issued read rows/seq:
// 4992 vs R6's 5632 (-11%), perfectly balanced (R10 showed balance lifts
// DRAM% to 73+). All ceiling-proven settings kept: scalar LDG lanes,
// 2048 warps in 64-thread blocks, depth-3 pipeline (48 LDGs in flight),
// normal STG stores.

#define B_DIM   32
#define T_DIM   4096
#define F_DIM   256
#define NCHUNK  8
#define L_MAIN  496
#define L_ZERO  624            // 624 + 7*496 = 4096
#define WARMUP  128
#define UB      16
#define NB      39             // batches per warp (identical for all warps)
#define PH_W    8              // warmup batches (chunks >= 1)
#define PH_ADJ  13             // adjusted batches (chunk 0): t < 208

#define ALPHA_C (2.0f / 26.0f)
#define OMA_C   (1.0f - ALPHA_C)

__device__ __forceinline__ void load_batch(float (&d)[UB],
                                           const float* __restrict__ p) {
#pragma unroll
    for (int i = 0; i < UB; i++)
        d[i] = __ldg(p + (size_t)i * F_DIM);
}

// Constant-coefficient batch (w_t == 1.0f exactly in fp32 for t >= 207).
__device__ __forceinline__ void proc_const(const float (&xv)[UB], float& e,
                                           float* __restrict__ po, bool st) {
#pragma unroll
    for (int i = 0; i < UB; i++) {
        e = fmaf(OMA_C, e, ALPHA_C * xv[i]);
        if (st) po[(size_t)i * F_DIM] = e;
    }
}

// Exact adjusted recurrence; p0 = oma^{t0} on entry. Reciprocals off-chain.
__device__ __forceinline__ void proc_adj(const float (&xv)[UB], float& e,
                                         float& p0, float* __restrict__ po) {
    float rw[UB];
    float q = 1.0f;
#pragma unroll
    for (int i = 0; i < UB; i++) {
        q *= OMA_C;                    // compile-time powers
        float wt = 1.0f - p0 * q;      // >= alpha, never degenerate
        rw[i] = __fdividef(1.0f, wt);
    }
    p0 *= q;
#pragma unroll
    for (int i = 0; i < UB; i++) {
        e = fmaf(OMA_C * rw[i], e, (ALPHA_C * rw[i]) * xv[i]);
        po[(size_t)i * F_DIM] = e;
    }
}

__global__ void __launch_bounds__(64)
ema_minbal_kernel(const float* __restrict__ x, float* __restrict__ out) {
    int g     = blockIdx.x * 64 + threadIdx.x;
    int lane  = g & 31;
    int w     = g >> 5;                 // warp id 0..2047
    int f_hi  = w & 7;
    int chunk = (w >> 3) & (NCHUNK - 1);
    int b     = w >> 6;
    int f     = f_hi * 32 + lane;
    bool isZ  = (chunk == 0);

    int t_store = isZ ? 0 : L_ZERO + (chunk - 1) * L_MAIN;
    int t_read  = isZ ? 0 : t_store - WARMUP;

    size_t seq_base = ((size_t)b * T_DIM) * F_DIM + f;
    const size_t STRIDE = (size_t)UB * F_DIM;
    const float* __restrict__ px = x   + seq_base + (size_t)t_read  * F_DIM;
    float*       __restrict__ po = out + seq_base + (size_t)t_store * F_DIM;

    float e  = 0.0f;
    float p0 = 1.0f;
    float bA[UB], bB[UB], bC[UB], bD[UB];

    load_batch(bA, px); px += STRIDE;
    load_batch(bB, px); px += STRIDE;
    load_batch(bC, px); px += STRIDE;

    // Batch j dispatch:
    //   chunk0, j <  PH_ADJ : adjusted, store
    //   chunk0, j >= PH_ADJ : constant, store  (t >= 208 -> w_t == 1.0f)
    //   other,  j <  PH_W   : constant, no store (warmup)
    //   other,  j >= PH_W   : constant, store
#define PROC(j, buf)                                                        \
    do {                                                                    \
        if (isZ && (j) < PH_ADJ) { proc_adj(buf, e, p0, po); po += STRIDE; }\
        else {                                                              \
            bool _st = isZ || ((j) >= PH_W);                                \
            proc_const(buf, e, po, _st);                                    \
            if (_st) po += STRIDE;                                          \
        }                                                                   \
    } while (0)

#pragma unroll 1
    for (int bt = 0; bt < NB - 3; bt += 4) {     // bt = 0,4,...,32 (9 iters)
        load_batch(bD, px); px += STRIDE;                    // batch bt+3
        PROC(bt, bA);
        if (bt + 4 < NB) { load_batch(bA, px); px += STRIDE; }
        PROC(bt + 1, bB);
        if (bt + 5 < NB) { load_batch(bB, px); px += STRIDE; }
        PROC(bt + 2, bC);
        if (bt + 6 < NB) { load_batch(bC, px); px += STRIDE; }
        PROC(bt + 3, bD);
    }
    // Epilogue: batches 36, 37, 38 (already loaded into bA, bB, bC)
    PROC(NB - 3, bA);
    PROC(NB - 2, bB);
    PROC(NB - 1, bC);
#undef PROC
}

extern "C" void kernel_launch(void* const* d_in, const int* in_sizes, int n_in,
                              void* d_out, int out_size) {
    const float* x = (const float*)d_in[0];
    float* out = (float*)d_out;
    // 32 b * 8 chunks * 8 f-groups = 2048 warps, 2 per block -> 1024 blocks
    ema_minbal_kernel<<<1024, 64>>>(x, out);
}